// round 5
// baseline (speedup 1.0000x reference)
#include <cuda_runtime.h>

#define BB   512
#define TM1  99
#define NF   128
#define HH   256
#define Z2W  100              // padded s-width for float4 stores
#define WOFF (BB*TM1*NF)      // offset of input_encoded in out

// ---------------- device scratch (no allocations allowed) ----------------
__device__ float  g_z2[BB*NF*Z2W];        // ~26 MB, layout [b][n][s(padded 100)]
__device__ float  g_h[2][BB*HH];          // ping-pong hidden
__device__ float  g_c[2][BB*HH];          // ping-pong cell
__device__ float4 g_Wt4[384*256];         // [k][j] -> (Wi,Wf,Wg,Wo) row j, col k
__device__ float  g_W2t[TM1*Z2W];         // W2 transposed [t][s], zero-padded s=99
__device__ float  g_bias[1024];           // b_ih + b_hh

// ---------------- fast math helpers (approx err ~2^-22, safe for 1e-3) ---
__device__ __forceinline__ float ex2f(float x){ float y; asm("ex2.approx.f32 %0, %1;" : "=f"(y) : "f"(x)); return y; }
__device__ __forceinline__ float rcpf(float x){ float y; asm("rcp.approx.f32 %0, %1;" : "=f"(y) : "f"(x)); return y; }
__device__ __forceinline__ float tanh_f(float x){
    float a  = fabsf(x);
    float em = ex2f(a * -2.8853900817779268f);      // e^{-2a}
    float r  = (1.0f - em) * rcpf(1.0f + em);
    return copysignf(r, x);
}
__device__ __forceinline__ float sigm_f(float x){
    float e = ex2f(x * -1.4426950408889634f);       // e^{-x}
    return rcpf(1.0f + e);
}
__device__ __forceinline__ float wsum(float v){
    #pragma unroll
    for (int o = 16; o; o >>= 1) v += __shfl_xor_sync(0xffffffffu, v, o);
    return v;
}
__device__ __forceinline__ float wmax(float v){
    #pragma unroll
    for (int o = 16; o; o >>= 1) v = fmaxf(v, __shfl_xor_sync(0xffffffffu, v, o));
    return v;
}

// ---------------- prep: transpose/fuse weights, zero initial state --------
__global__ void prep_kernel(const float* __restrict__ W_ih, const float* __restrict__ W_hh,
                            const float* __restrict__ b_ih, const float* __restrict__ b_hh,
                            const float* __restrict__ W2)
{
    int stride = gridDim.x * blockDim.x;
    int tid0   = blockIdx.x * blockDim.x + threadIdx.x;

    // interleaved transposed LSTM weights: g_Wt4[k*256 + j] = (row j, row 256+j, 512+j, 768+j) at col k
    for (int idx = tid0; idx < 384*256; idx += stride) {
        int k = idx >> 8, j = idx & 255;
        float4 v;
        if (k < 128) {
            v.x = W_ih[(j      )*128 + k];
            v.y = W_ih[(j + 256)*128 + k];
            v.z = W_ih[(j + 512)*128 + k];
            v.w = W_ih[(j + 768)*128 + k];
        } else {
            int kk = k - 128;
            v.x = W_hh[(j      )*256 + kk];
            v.y = W_hh[(j + 256)*256 + kk];
            v.z = W_hh[(j + 512)*256 + kk];
            v.w = W_hh[(j + 768)*256 + kk];
        }
        g_Wt4[idx] = v;
    }
    // W2 transposed + zero pad
    for (int idx = tid0; idx < TM1*Z2W; idx += stride) {
        int t = idx / Z2W, s = idx - t*Z2W;
        g_W2t[idx] = (s < TM1) ? W2[s*TM1 + t] : 0.0f;
    }
    // fused bias
    for (int idx = tid0; idx < 1024; idx += stride)
        g_bias[idx] = b_ih[idx] + b_hh[idx];
    // zero initial h, c (buffer 0)
    for (int idx = tid0; idx < BB*HH; idx += stride) {
        g_h[0][idx] = 0.0f;
        g_c[0][idx] = 0.0f;
    }
}

// ---------------- z2 precompute: z2[b][n][s] = sum_t in[b,t,n]*W2[s,t]+b2[s]
// grid: 1024 blocks = (b, n-half), 256 threads
__global__ void z2_kernel(const float* __restrict__ in, const float* __restrict__ b2)
{
    __shared__ float inT[64*TM1];    // [nn][t]
    int b  = blockIdx.x >> 1;
    int nh = blockIdx.x & 1;
    int tid = threadIdx.x;

    for (int i = tid; i < 64*TM1; i += 256) {
        int t = i >> 6, nn = i & 63;
        inT[nn*TM1 + t] = in[b*TM1*NF + t*NF + nh*64 + nn];
    }
    __syncthreads();

    int w = tid >> 5, l = tid & 31;
    if (l < 25) {
        int s0 = 4*l;
        float4 bb;
        bb.x = (s0+0 < TM1) ? b2[s0+0] : 0.0f;
        bb.y = (s0+1 < TM1) ? b2[s0+1] : 0.0f;
        bb.z = (s0+2 < TM1) ? b2[s0+2] : 0.0f;
        bb.w = (s0+3 < TM1) ? b2[s0+3] : 0.0f;
        const float4* wrow = (const float4*)g_W2t;   // [t][25 float4]
        for (int nn = w*8; nn < w*8 + 8; nn++) {
            float4 acc = make_float4(0.f,0.f,0.f,0.f);
            #pragma unroll 3
            for (int t = 0; t < TM1; t++) {
                float  xv = inT[nn*TM1 + t];
                float4 wv = wrow[t*25 + l];
                acc.x = fmaf(xv, wv.x, acc.x);
                acc.y = fmaf(xv, wv.y, acc.y);
                acc.z = fmaf(xv, wv.z, acc.z);
                acc.w = fmaf(xv, wv.w, acc.w);
            }
            acc.x += bb.x; acc.y += bb.y; acc.z += bb.z; acc.w += bb.w;
            int n = nh*64 + nn;
            *(float4*)&g_z2[(b*NF + n)*Z2W + s0] = acc;
        }
    }
}

// ---------------- attention kernel (per step): z1 -> e -> softmax -> w ----
// grid: 128 blocks x 4 batches, 256 threads (8 warps)
__global__ void attn_kernel(int t, const float* __restrict__ in,
                            const float* __restrict__ W1, const float* __restrict__ b1,
                            const float* __restrict__ W3, const float* __restrict__ b3,
                            float* __restrict__ out)
{
    __shared__ float hc[4*512];      // [bi][512] = [h(256); c(256)]
    __shared__ float z1s[4*128];
    __shared__ float es[4*128];

    int tid = threadIdx.x, w = tid >> 5, l = tid & 31;
    int b0  = blockIdx.x * 4;
    const float* hsrc = g_h[t & 1];
    const float* csrc = g_c[t & 1];

    for (int i = tid; i < 4*512; i += 256) {
        int bi = i >> 9, j = i & 511;
        hc[i] = (j < 256) ? hsrc[(b0+bi)*HH + j] : csrc[(b0+bi)*HH + (j-256)];
    }
    __syncthreads();

    // hoist this lane's hc slice into registers (fixed across s)
    float4 hr[4][4];
    #pragma unroll
    for (int bi = 0; bi < 4; bi++) {
        const float4* h4 = (const float4*)(hc + bi*512);
        #pragma unroll
        for (int u = 0; u < 4; u++) hr[bi][u] = h4[l + 32*u];
    }

    // stage 1: z1[bi][s] = dot(hc[bi], W1[s]) + b1[s]
    for (int s = w; s < TM1; s += 8) {
        const float4* wr = (const float4*)(W1 + s*512);
        float4 w0 = wr[l], w1 = wr[l+32], w2 = wr[l+64], w3v = wr[l+96];
        float bv = b1[s];
        #pragma unroll
        for (int bi = 0; bi < 4; bi++) {
            float a = 0.0f;
            a = fmaf(w0.x, hr[bi][0].x, a); a = fmaf(w0.y, hr[bi][0].y, a);
            a = fmaf(w0.z, hr[bi][0].z, a); a = fmaf(w0.w, hr[bi][0].w, a);
            a = fmaf(w1.x, hr[bi][1].x, a); a = fmaf(w1.y, hr[bi][1].y, a);
            a = fmaf(w1.z, hr[bi][1].z, a); a = fmaf(w1.w, hr[bi][1].w, a);
            a = fmaf(w2.x, hr[bi][2].x, a); a = fmaf(w2.y, hr[bi][2].y, a);
            a = fmaf(w2.z, hr[bi][2].z, a); a = fmaf(w2.w, hr[bi][2].w, a);
            a = fmaf(w3v.x, hr[bi][3].x, a); a = fmaf(w3v.y, hr[bi][3].y, a);
            a = fmaf(w3v.z, hr[bi][3].z, a); a = fmaf(w3v.w, hr[bi][3].w, a);
            a = wsum(a);
            if (l == 0) z1s[bi*128 + s] = a + bv;
        }
    }
    __syncthreads();

    // stage 2: e[bi][n] = sum_s W3[s]*tanh(z1[s] + z2[b,n,s]) + b3
    for (int idx = w; idx < 512; idx += 8) {
        int bi = idx >> 7, n = idx & 127;
        const float* zrow = g_z2 + ((b0+bi)*NF + n)*Z2W;
        const float* z1r  = z1s + bi*128;
        float acc = 0.0f;
        int s;
        s = l;      acc = fmaf(W3[s], tanh_f(z1r[s] + zrow[s]), acc);
        s = l + 32; acc = fmaf(W3[s], tanh_f(z1r[s] + zrow[s]), acc);
        s = l + 64; acc = fmaf(W3[s], tanh_f(z1r[s] + zrow[s]), acc);
        if (l < 3) { s = l + 96; acc = fmaf(W3[s], tanh_f(z1r[s] + zrow[s]), acc); }
        acc = wsum(acc);
        if (l == 0) es[bi*128 + n] = acc + b3[0];
    }
    __syncthreads();

    // stage 3: softmax over n, w = attn * x_t, store input_weighted
    if (w < 4) {
        int bi = w, b = b0 + bi;
        float v0 = es[bi*128 + l],      v1 = es[bi*128 + 32 + l];
        float v2 = es[bi*128 + 64 + l], v3 = es[bi*128 + 96 + l];
        float m = fmaxf(fmaxf(v0, v1), fmaxf(v2, v3));
        m = wmax(m);
        float e0 = ex2f((v0 - m) * 1.4426950408889634f);
        float e1 = ex2f((v1 - m) * 1.4426950408889634f);
        float e2 = ex2f((v2 - m) * 1.4426950408889634f);
        float e3 = ex2f((v3 - m) * 1.4426950408889634f);
        float sum = wsum(e0 + e1 + e2 + e3);
        float r = rcpf(sum);
        const float* xrow = in  + b*TM1*NF + t*NF;
        float*       orow = out + b*TM1*NF + t*NF;
        orow[l     ] = e0 * r * xrow[l     ];
        orow[l + 32] = e1 * r * xrow[l + 32];
        orow[l + 64] = e2 * r * xrow[l + 64];
        orow[l + 96] = e3 * r * xrow[l + 96];
    }
}

// ---------------- LSTM kernel (per step): gates GEMM + cell update --------
// grid: 128 blocks = 32 batch-tiles(16) x 4 hidden-tiles(64), 256 threads
__global__ void lstm_kernel(int t, float* __restrict__ out)
{
    __shared__ float xs[16*384];     // [bb][k] : k<128 -> w, k>=128 -> h
    int tid   = threadIdx.x;
    int btile = blockIdx.x & 31;
    int htile = blockIdx.x >> 5;

    const float* hsrc = g_h[t & 1];
    const float* csrc = g_c[t & 1];
    float*       hdst = g_h[(t + 1) & 1];
    float*       cdst = g_c[(t + 1) & 1];

    for (int i = tid; i < 16*384; i += 256) {
        int bb = i / 384, k = i - bb*384;
        int b  = btile*16 + bb;
        float v = (k < 128) ? out[b*TM1*NF + t*NF + k] : hsrc[b*HH + (k - 128)];
        xs[bb*384 + k] = v;
    }
    __syncthreads();

    int hu = tid & 63, bg = tid >> 6;
    int j  = htile*64 + hu;

    float bI = g_bias[j], bF = g_bias[256 + j], bG = g_bias[512 + j], bO = g_bias[768 + j];
    float aI[4] = {bI, bI, bI, bI};
    float aF[4] = {bF, bF, bF, bF};
    float aG[4] = {bG, bG, bG, bG};
    float aO[4] = {bO, bO, bO, bO};

    const float* x0 = xs + (bg*4 + 0)*384;
    const float* x1 = xs + (bg*4 + 1)*384;
    const float* x2 = xs + (bg*4 + 2)*384;
    const float* x3 = xs + (bg*4 + 3)*384;

    #pragma unroll 4
    for (int k = 0; k < 384; k++) {
        float4 wv = g_Wt4[k*256 + j];
        float xv0 = x0[k], xv1 = x1[k], xv2 = x2[k], xv3 = x3[k];
        aI[0] = fmaf(wv.x, xv0, aI[0]); aI[1] = fmaf(wv.x, xv1, aI[1]);
        aI[2] = fmaf(wv.x, xv2, aI[2]); aI[3] = fmaf(wv.x, xv3, aI[3]);
        aF[0] = fmaf(wv.y, xv0, aF[0]); aF[1] = fmaf(wv.y, xv1, aF[1]);
        aF[2] = fmaf(wv.y, xv2, aF[2]); aF[3] = fmaf(wv.y, xv3, aF[3]);
        aG[0] = fmaf(wv.z, xv0, aG[0]); aG[1] = fmaf(wv.z, xv1, aG[1]);
        aG[2] = fmaf(wv.z, xv2, aG[2]); aG[3] = fmaf(wv.z, xv3, aG[3]);
        aO[0] = fmaf(wv.w, xv0, aO[0]); aO[1] = fmaf(wv.w, xv1, aO[1]);
        aO[2] = fmaf(wv.w, xv2, aO[2]); aO[3] = fmaf(wv.w, xv3, aO[3]);
    }

    #pragma unroll
    for (int m = 0; m < 4; m++) {
        int b = btile*16 + bg*4 + m;
        float iv = sigm_f(aI[m]);
        float fv = sigm_f(aF[m]);
        float gv = tanh_f(aG[m]);
        float ov = sigm_f(aO[m]);
        float cold = csrc[b*HH + j];
        float cn = fmaf(fv, cold, iv * gv);
        float hn = ov * tanh_f(cn);
        cdst[b*HH + j] = cn;
        hdst[b*HH + j] = hn;
        out[WOFF + b*TM1*HH + t*HH + j] = hn;
    }
}

// ---------------- launch ---------------------------------------------------
extern "C" void kernel_launch(void* const* d_in, const int* in_sizes, int n_in,
                              void* d_out, int out_size)
{
    const float* in   = (const float*)d_in[0];
    const float* W1   = (const float*)d_in[1];
    const float* b1   = (const float*)d_in[2];
    const float* W2   = (const float*)d_in[3];
    const float* b2   = (const float*)d_in[4];
    const float* W3   = (const float*)d_in[5];
    const float* b3   = (const float*)d_in[6];
    const float* W_ih = (const float*)d_in[7];
    const float* W_hh = (const float*)d_in[8];
    const float* b_ih = (const float*)d_in[9];
    const float* b_hh = (const float*)d_in[10];
    float* out = (float*)d_out;

    prep_kernel<<<148, 256>>>(W_ih, W_hh, b_ih, b_hh, W2);
    z2_kernel<<<1024, 256>>>(in, b2);
    for (int t = 0; t < TM1; t++) {
        attn_kernel<<<128, 256>>>(t, in, W1, b1, W3, b3, out);
        lstm_kernel<<<128, 256>>>(t, out);
    }
}